// round 12
// baseline (speedup 1.0000x reference)
#include <cuda_runtime.h>
#include <cuda_fp16.h>
#include <math.h>

#define NBATCH 64
#define NCAT   128
#define NK     127
#define NTYPE  6
#define NCH    36
#define NUNIT  (NCAT * NK)       // 16256 (n,j) units
#define NSLOT  (NUNIT * 2)       // 32512 warp-slots (2 batch halves per unit)
#define NPLAN  (NSLOT + NCH * 4) // padded plan capacity (32656)
#define NBLK1  (NPLAN / 4)       // K1 blocks (8164)

#define TSCL 2.885390081777927f  // 2*log2(e) — folded into LAYER-1 weights only

// smem strides (halfs) — conflict-free for fragment loads
#define SA  40   // A1 (y1) rows: 32 cols used
#define SW2 40   // W2h rows: 32 cols used
#define SW3 72   // W3h rows: 64 cols used
#define SY  72   // Y2 rows: 64 cols used

// g_W1  [64] fp32: [0,25)=TSCL*W1, [25,50)=TSCL*b1        (layer1 uses tanhS)
// g_Wh2 [56*40] half UNSCALED: k<25=W2, k==25=b2, else 0  (layer2 uses tanh.f16x2)
// g_Wh3 [104*72] half UNSCALED: k<50=W3, k==50=b3, else 0 (layer3 uses tanh.f16x2)
__device__ float  g_W1[NCH * 64];
__device__ __half g_Wh2[NCH * 56 * SW2];
__device__ __half g_Wh3[NCH * 104 * SW3];
__device__ int    g_plan[NPLAN];
__device__ int    g_sinv[NSLOT];                       // slot value -> plan position
__device__ __half g_out[(size_t)NPLAN * 32 * 100];     // sample-major MLP outputs

// tanh on PRE-SCALED input s = 2*log2e*v : 1 - 2*rcp(2^s + 1)
__device__ __forceinline__ float tanhS(float s) {
    float e;
    asm("ex2.approx.ftz.f32 %0, %1;" : "=f"(e) : "f"(s));
    float r;
    asm("rcp.approx.ftz.f32 %0, %1;" : "=f"(r) : "f"(e + 1.0f));
    return fmaf(-2.0f, r, 1.0f);
}
// hardware half2 tanh: 1 MUFU for 2 activations
__device__ __forceinline__ __half2 tanh_h2(__half2 x) {
    unsigned r, xi = *(unsigned*)&x;
    asm("tanh.approx.f16x2 %0, %1;" : "=r"(r) : "r"(xi));
    return *(__half2*)&r;
}

__device__ __forceinline__ void mma16816(float c[4], const unsigned a[4],
                                         unsigned b0, unsigned b1) {
    asm volatile(
        "mma.sync.aligned.m16n8k16.row.col.f32.f16.f16.f32 "
        "{%0,%1,%2,%3}, {%4,%5,%6,%7}, {%8,%9}, {%0,%1,%2,%3};"
        : "+f"(c[0]), "+f"(c[1]), "+f"(c[2]), "+f"(c[3])
        : "r"(a[0]), "r"(a[1]), "r"(a[2]), "r"(a[3]), "r"(b0), "r"(b1));
}

// ---------------- prep: weight packs (layer1 scaled; layers 2/3 raw) ----------------
__global__ void prep_packh(const float* __restrict__ W1, const float* __restrict__ b1,
                           const float* __restrict__ W2, const float* __restrict__ b2,
                           const float* __restrict__ W3, const float* __restrict__ b3) {
    const int S1 = NCH * 64;
    const int S2 = NCH * 56 * SW2;
    const int S3 = NCH * 104 * SW3;
    for (int i = blockIdx.x * blockDim.x + threadIdx.x; i < S1 + S2 + S3;
         i += gridDim.x * blockDim.x) {
        if (i < S1) {
            int ch = i / 64, r = i % 64;
            float v = 0.0f;
            if (r < 25)      v = TSCL * W1[ch * 25 + r];
            else if (r < 50) v = TSCL * b1[ch * 25 + (r - 25)];
            g_W1[i] = v;
        } else if (i < S1 + S2) {
            int ii = i - S1;
            int ch = ii / (56 * SW2), rr = ii % (56 * SW2);
            int o = rr / SW2, k = rr % SW2;
            float v = 0.0f;
            if (o < 50) {
                if (k < 25)       v = W2[(ch * 50 + o) * 25 + k];
                else if (k == 25) v = b2[ch * 50 + o];
            }
            g_Wh2[ii] = __float2half(v);
        } else {
            int ii = i - S1 - S2;
            int ch = ii / (104 * SW3), rr = ii % (104 * SW3);
            int o = rr / SW3, k = rr % SW3;
            float v = 0.0f;
            if (o < 100) {
                if (k < 50)       v = W3[(ch * 100 + o) * 50 + k];
                else if (k == 50) v = b3[ch * 100 + o];
            }
            g_Wh3[ii] = __float2half(v);
        }
    }
}

// ---------------- prep: channel-pure warp-slot plan + inverse map ----------------
__global__ void prep_plan(const int* __restrict__ types) {
    __shared__ int ts[NCAT];
    __shared__ int cnt[NCH];
    __shared__ int off[NCH];
    int t = threadIdx.x;

    for (int i = t; i < NPLAN; i += 256) g_plan[i] = -1;
    if (t < NCAT) ts[t] = types[t];
    if (t < NCH)  cnt[t] = 0;
    __syncthreads();

    for (int u = t; u < NUNIT; u += 256) {
        int n = u / NK, k = u % NK;
        int j = k + (k >= n ? 1 : 0);
        atomicAdd(&cnt[ts[n] * NTYPE + ts[j]], 2);
    }
    __syncthreads();
    if (t == 0) {
        int run = 0;
        for (int c = 0; c < NCH; c++) {
            off[c] = run;
            run += (cnt[c] + 3) & ~3;
        }
    }
    __syncthreads();
    for (int u = t; u < NUNIT; u += 256) {
        int n = u / NK, k = u % NK;
        int j = k + (k >= n ? 1 : 0);
        int c = ts[n] * NTYPE + ts[j];
        int pos = atomicAdd(&off[c], 2);
        g_plan[pos]     = u * 2;
        g_plan[pos + 1] = u * 2 + 1;
        g_sinv[u * 2]     = pos;
        g_sinv[u * 2 + 1] = pos + 1;
    }
}

// ---------------- K1: channel-pure MLP via m16n8k16 tensor GEMMs ----------------
__global__ __launch_bounds__(128, 4)
void k1_mlp(const float* __restrict__ coords, const int* __restrict__ types) {
    __shared__ __align__(16) float  W1f[64];
    __shared__ __align__(16) __half A1[128 * SA];
    __shared__ __align__(16) __half W2h[56 * SW2];
    __shared__ __align__(16) __half W3h[104 * SW3];
    __shared__ __align__(16) __half Y2[128 * SY];

    const int tid  = threadIdx.x;
    const int wid  = tid >> 5;
    const int lane = tid & 31;
    const int gid  = lane >> 2;        // fragment row group
    const int qc   = (lane & 3) * 2;   // fragment col pair

    const int slot0 = g_plan[blockIdx.x * 4];
    if (slot0 < 0) return;             // fully-padding block

    int ch;
    {
        int u0 = slot0 >> 1;
        int n0 = u0 / NK, k0 = u0 % NK;
        int j0 = k0 + (k0 >= n0 ? 1 : 0);
        ch = types[n0] * NTYPE + types[j0];
    }

    // stage per-channel weights
    if (tid < 16) ((uint4*)W1f)[tid] = ((const uint4*)(g_W1 + ch * 64))[tid];
    {
        const uint4* s2 = (const uint4*)(g_Wh2 + (size_t)ch * 56 * SW2);
        for (int i = tid; i < 56 * SW2 / 8; i += 128) ((uint4*)W2h)[i] = s2[i];
        const uint4* s3 = (const uint4*)(g_Wh3 + (size_t)ch * 104 * SW3);
        for (int i = tid; i < 104 * SW3 / 8; i += 128) ((uint4*)W3h)[i] = s3[i];
    }

    int slot = g_plan[blockIdx.x * 4 + wid];
    if (slot < 0) slot = slot0;        // padding warp: safe same-channel fallback
    const int u  = slot >> 1;
    const int un = u / NK;
    const int uk = u % NK;
    const int uj = uk + (uk >= un ? 1 : 0);
    const int b  = lane + ((slot & 1) << 5);

    // per-sample input x
    const float* cb = coords + (size_t)b * NCAT * 3;
    float rx = cb[un * 3 + 0] - cb[uj * 3 + 0];
    float ry = cb[un * 3 + 1] - cb[uj * 3 + 1];
    float rz = cb[un * 3 + 2] - cb[uj * 3 + 2];
    float d  = sqrtf(rx * rx + ry * ry + rz * rz);
    float x  = 1.0f / fmaxf(d, 1e-12f);

    __syncthreads();   // weights staged

    // ---- layer 1 (fp32 tanhS, pre-scaled weights) -> A1 fp16; col 25 = 1.0 ----
    {
        __half* row = A1 + tid * SA;
#pragma unroll
        for (int q = 0; q < 12; q++) {
            float v0 = tanhS(fmaf(W1f[2 * q],     x, W1f[25 + 2 * q]));
            float v1 = tanhS(fmaf(W1f[2 * q + 1], x, W1f[25 + 2 * q + 1]));
            *(__half2*)(row + 2 * q) = __floats2half2_rn(v0, v1);
        }
        float v24 = tanhS(fmaf(W1f[24], x, W1f[49]));
        *(__half2*)(row + 24) = __floats2half2_rn(v24, 1.0f);
        *(__half2*)(row + 26) = __floats2half2_rn(0.0f, 0.0f);
        *(__half2*)(row + 28) = __floats2half2_rn(0.0f, 0.0f);
        *(__half2*)(row + 30) = __floats2half2_rn(0.0f, 0.0f);
        // Y2 pad: col 50 = 1.0 (bias input), cols 51..63 = 0
        __half* yrow = Y2 + tid * SY;
        *(__half2*)(yrow + 50) = __floats2half2_rn(1.0f, 0.0f);
#pragma unroll
        for (int c = 52; c < 64; c += 2)
            *(__half2*)(yrow + c) = __floats2half2_rn(0.0f, 0.0f);
    }
    __syncthreads();

    const int RB = wid * 32;   // this warp's 32 sample rows

    // ---- layer 2 GEMM: Y2[128x50] = tanh(A1[128x26] * W2^T) + concat(y1,y1) ----
    {
        unsigned aF[2][2][4];
#pragma unroll
        for (int mt = 0; mt < 2; mt++)
#pragma unroll
            for (int kt = 0; kt < 2; kt++) {
                const __half* base = A1 + (RB + mt * 16 + gid) * SA + kt * 16 + qc;
                aF[mt][kt][0] = *(const unsigned*)(base);
                aF[mt][kt][1] = *(const unsigned*)(base + 8 * SA);
                aF[mt][kt][2] = *(const unsigned*)(base + 8);
                aF[mt][kt][3] = *(const unsigned*)(base + 8 * SA + 8);
            }
#pragma unroll
        for (int nt = 0; nt < 7; nt++) {
            float c0[4] = {0.f, 0.f, 0.f, 0.f};
            float c1[4] = {0.f, 0.f, 0.f, 0.f};
#pragma unroll
            for (int kt = 0; kt < 2; kt++) {
                const __half* wb = W2h + (nt * 8 + gid) * SW2 + kt * 16 + qc;
                unsigned b0 = *(const unsigned*)(wb);
                unsigned b1 = *(const unsigned*)(wb + 8);
                mma16816(c0, aF[0][kt], b0, b1);
                mma16816(c1, aF[1][kt], b0, b1);
            }
            int n0 = nt * 8 + qc;
            if (n0 < 50) {
                int i0 = (n0 < 25) ? n0 : n0 - 25;
                int i1 = (n0 + 1 < 25) ? n0 + 1 : n0 + 1 - 25;
#pragma unroll
                for (int mt = 0; mt < 2; mt++) {
                    const float* cc = mt ? c1 : c0;
                    int r = RB + mt * 16 + gid;
                    __half2 t0 = tanh_h2(__floats2half2_rn(cc[0], cc[1]));
                    __half2 e0 = __halves2half2(A1[r * SA + i0], A1[r * SA + i1]);
                    *(__half2*)(Y2 + r * SY + n0) = __hadd2(t0, e0);
                    r += 8;
                    __half2 t1 = tanh_h2(__floats2half2_rn(cc[2], cc[3]));
                    __half2 e1 = __halves2half2(A1[r * SA + i0], A1[r * SA + i1]);
                    *(__half2*)(Y2 + r * SY + n0) = __hadd2(t1, e1);
                }
            }
        }
    }
    __syncthreads();

    // ---- layer 3 GEMM: out[128x100] = tanh(Y2[128x51] * W3^T) + concat(y2,y2) ----
    {
        unsigned aG[2][4][4];
#pragma unroll
        for (int mt = 0; mt < 2; mt++)
#pragma unroll
            for (int kt = 0; kt < 4; kt++) {
                const __half* base = Y2 + (RB + mt * 16 + gid) * SY + kt * 16 + qc;
                aG[mt][kt][0] = *(const unsigned*)(base);
                aG[mt][kt][1] = *(const unsigned*)(base + 8 * SY);
                aG[mt][kt][2] = *(const unsigned*)(base + 8);
                aG[mt][kt][3] = *(const unsigned*)(base + 8 * SY + 8);
            }
        const size_t gbase = (size_t)blockIdx.x * 128;  // sample-major output rows
#pragma unroll
        for (int nt = 0; nt < 13; nt++) {
            float c0[4] = {0.f, 0.f, 0.f, 0.f};
            float c1[4] = {0.f, 0.f, 0.f, 0.f};
#pragma unroll
            for (int kt = 0; kt < 4; kt++) {
                const __half* wb = W3h + (nt * 8 + gid) * SW3 + kt * 16 + qc;
                unsigned b0 = *(const unsigned*)(wb);
                unsigned b1 = *(const unsigned*)(wb + 8);
                mma16816(c0, aG[0][kt], b0, b1);
                mma16816(c1, aG[1][kt], b0, b1);
            }
            int n0 = nt * 8 + qc;
            if (n0 < 100) {
                // i0 even, i1 = i0+1 contiguous -> aligned half2 residual load
                int i0 = (n0 < 50) ? n0 : n0 - 50;
#pragma unroll
                for (int mt = 0; mt < 2; mt++) {
                    const float* cc = mt ? c1 : c0;
                    int r = RB + mt * 16 + gid;
                    __half2 t0 = tanh_h2(__floats2half2_rn(cc[0], cc[1]));
                    __half2 e0 = *(const __half2*)(Y2 + r * SY + i0);
                    *(__half2*)(g_out + (gbase + r) * 100 + n0) = __hadd2(t0, e0);
                    r += 8;
                    __half2 t1 = tanh_h2(__floats2half2_rn(cc[2], cc[3]));
                    __half2 e1 = *(const __half2*)(Y2 + r * SY + i0);
                    *(__half2*)(g_out + (gbase + r) * 100 + n0) = __hadd2(t1, e1);
                }
            }
        }
    }
}

// ---------------- K2: res[g][f] = sum_a M[g][a]*M[f][a], M = out^T * a ----------------
__global__ __launch_bounds__(128)
void k2_contract(const float* __restrict__ coords, float* __restrict__ outp) {
    __shared__ float cs[NCAT * 3];
    __shared__ float as_[NK * 3];
    __shared__ int   sk[NK];
    __shared__ float Mpart[4][25][12];
    __shared__ float Ms[100 * 3];

    const int n   = blockIdx.x;
    const int b   = blockIdx.y;
    const int tid = threadIdx.x;
    const int warp = tid >> 5, lane = tid & 31;
    const int half = b >> 5, bl = b & 31;

    for (int i = tid; i < NCAT * 3; i += 128)
        cs[i] = coords[(size_t)b * NCAT * 3 + i];
    if (tid < NK)
        sk[tid] = g_sinv[(n * NK + tid) * 2 + half] * 32 + bl;
    __syncthreads();

    if (tid < NK) {
        int k = tid;
        int j = k + (k >= n ? 1 : 0);
        float rx = cs[n * 3 + 0] - cs[j * 3 + 0];
        float ry = cs[n * 3 + 1] - cs[j * 3 + 1];
        float rz = cs[n * 3 + 2] - cs[j * 3 + 2];
        float d  = sqrtf(rx * rx + ry * ry + rz * rz);
        float dinv = 1.0f / fmaxf(d, 1e-12f);
        float s = dinv * dinv;
        as_[k * 3 + 0] = rx * s;
        as_[k * 3 + 1] = ry * s;
        as_[k * 3 + 2] = rz * s;
    }
    __syncthreads();

    float acc[12];
#pragma unroll
    for (int i = 0; i < 12; i++) acc[i] = 0.0f;

    if (lane < 25) {
        for (int kk = warp; kk < NK; kk += 4) {
            uint2 pr = *(const uint2*)(g_out + (size_t)sk[kk] * 100 + lane * 4);
            __half2 h01 = *(__half2*)&pr.x;
            __half2 h23 = *(__half2*)&pr.y;
            float2 f01 = __half22float2(h01);
            float2 f23 = __half22float2(h23);
            float a0 = as_[kk * 3 + 0];
            float a1 = as_[kk * 3 + 1];
            float a2 = as_[kk * 3 + 2];
            acc[0]  = fmaf(f01.x, a0, acc[0]);
            acc[1]  = fmaf(f01.x, a1, acc[1]);
            acc[2]  = fmaf(f01.x, a2, acc[2]);
            acc[3]  = fmaf(f01.y, a0, acc[3]);
            acc[4]  = fmaf(f01.y, a1, acc[4]);
            acc[5]  = fmaf(f01.y, a2, acc[5]);
            acc[6]  = fmaf(f23.x, a0, acc[6]);
            acc[7]  = fmaf(f23.x, a1, acc[7]);
            acc[8]  = fmaf(f23.x, a2, acc[8]);
            acc[9]  = fmaf(f23.y, a0, acc[9]);
            acc[10] = fmaf(f23.y, a1, acc[10]);
            acc[11] = fmaf(f23.y, a2, acc[11]);
        }
#pragma unroll
        for (int i = 0; i < 12; i++) Mpart[warp][lane][i] = acc[i];
    }
    __syncthreads();

    float m0 = 0.0f, m1 = 0.0f, m2 = 0.0f;
    if (tid < 100) {
        const int quad = tid >> 2, e = tid & 3;
#pragma unroll
        for (int w = 0; w < 4; w++) {
            m0 += Mpart[w][quad][e * 3 + 0];
            m1 += Mpart[w][quad][e * 3 + 1];
            m2 += Mpart[w][quad][e * 3 + 2];
        }
        Ms[tid * 3 + 0] = m0;
        Ms[tid * 3 + 1] = m1;
        Ms[tid * 3 + 2] = m2;
    }
    __syncthreads();

    if (tid < 100) {
        float4 r;
        r.x = m0 * Ms[0] + m1 * Ms[1]  + m2 * Ms[2];
        r.y = m0 * Ms[3] + m1 * Ms[4]  + m2 * Ms[5];
        r.z = m0 * Ms[6] + m1 * Ms[7]  + m2 * Ms[8];
        r.w = m0 * Ms[9] + m1 * Ms[10] + m2 * Ms[11];
        *(float4*)(outp + ((size_t)(b * NCAT + n)) * 400 + tid * 4) = r;
    }
}

extern "C" void kernel_launch(void* const* d_in, const int* in_sizes, int n_in,
                              void* d_out, int out_size) {
    const float* coords     = (const float*)d_in[0];
    const int*   atom_types = (const int*)d_in[1];
    const float* W1 = (const float*)d_in[2];
    const float* b1 = (const float*)d_in[3];
    const float* W2 = (const float*)d_in[4];
    const float* b2 = (const float*)d_in[5];
    const float* W3 = (const float*)d_in[6];
    const float* b3 = (const float*)d_in[7];
    float* outp = (float*)d_out;

    prep_packh<<<1024, 256>>>(W1, b1, W2, b2, W3, b3);
    prep_plan<<<1, 256>>>(atom_types);
    k1_mlp<<<NBLK1, 128>>>(coords, atom_types);
    k2_contract<<<dim3(NCAT, NBATCH), 128>>>(coords, outp);
}